// round 15
// baseline (speedup 1.0000x reference)
#include <cuda_runtime.h>

#define NN 100000
#define EE 1600000
#define KHOP 50
#define SCAN_BS 1024
#define NBLK_SCAN ((NN + SCAN_BS - 1) / SCAN_BS)
#define CSCSZ (EE + 7 * NN + 64)   // deg padded to multiple of 8

// ---------------- device scratch (static, no allocation) ----------------
__device__ float g_deg[NN];
__device__ float g_dis[NN];
__device__ int   g_cnt[NN];
__device__ int   g_off[NN + 1];
__device__ int   g_cur[NN];
__device__ int   g_bsum[NBLK_SCAN];
__device__ int   g_boff[NBLK_SCAN];
__device__ __align__(16) int2 g_csc[CSCSZ];          // {src, bitcast(norm)}; zero-padded
__device__ float g_h1[(KHOP + 1) * NN * 2];          // layer-1 hop history (2-wide)
__device__ float g_h2[(size_t)(KHOP + 1) * NN * 16]; // layer-2 hop history (16-wide)
__device__ float g_z3[(size_t)(KHOP + 1) * NN * 16]; // layer-3 z_k = x3 W3_k (16-wide)
__device__ float g_ha[NN * 16];                      // layer-3 Horner ping
__device__ float g_hb[NN * 16];                      // layer-3 Horner pong
__device__ float g_z4[(KHOP + 1) * NN];
__device__ float g_t4a[NN];
__device__ float g_t4b[NN];

// ---------------- f32x2 packed helpers (bitwise-identical fp32 math) --------
__device__ __forceinline__ unsigned long long pk2(float lo, float hi) {
    unsigned long long r;
    asm("mov.b64 %0, {%1, %2};" : "=l"(r) : "f"(lo), "f"(hi));
    return r;
}
__device__ __forceinline__ void upk2(float& lo, float& hi, unsigned long long v) {
    asm("mov.b64 {%0, %1}, %2;" : "=f"(lo), "=f"(hi) : "l"(v));
}
__device__ __forceinline__ void fma2(unsigned long long& d, unsigned long long a,
                                     unsigned long long b) {
    asm("fma.rn.f32x2 %0, %1, %2, %0;" : "+l"(d) : "l"(a), "l"(b));
}

// ---------------- setup kernels ----------------
__global__ void k_init0() {
    int i = blockIdx.x * blockDim.x + threadIdx.x;
    if (i < NN) { g_deg[i] = 0.f; g_cnt[i] = 0; }
    if (i < CSCSZ / 2) ((int4*)g_csc)[i] = make_int4(0, 0, 0, 0);
}

__global__ void k_degcnt(const int* __restrict__ ei, const float* __restrict__ ew) {
    int e = blockIdx.x * blockDim.x + threadIdx.x;
    if (e < EE) {
        int c = ei[EE + e];
        atomicAdd(&g_deg[c], ew[e]);
        atomicAdd(&g_cnt[c], 1);
    }
}

// per-block sums of PADDED counts + fused g_dis computation
__global__ void k_bsum() {
    __shared__ int ws[32];
    int tid = threadIdx.x, lane = tid & 31, wid = tid >> 5;
    int i = blockIdx.x * SCAN_BS + tid;
    int v = 0;
    if (i < NN) {
        v = (g_cnt[i] + 7) & ~7;
        float d = g_deg[i];
        g_dis[i] = (d > 0.f) ? (1.0f / sqrtf(d)) : 0.f;
    }
    #pragma unroll
    for (int d = 16; d >= 1; d >>= 1) v += __shfl_down_sync(0xffffffffu, v, d);
    if (lane == 0) ws[wid] = v;
    __syncthreads();
    if (wid == 0) {
        int y = ws[lane];
        #pragma unroll
        for (int d = 16; d >= 1; d >>= 1) y += __shfl_down_sync(0xffffffffu, y, d);
        if (lane == 0) g_bsum[blockIdx.x] = y;
    }
}

__global__ void k_bscan() {
    __shared__ int ws[4];
    int tid = threadIdx.x, lane = tid & 31, wid = tid >> 5;
    int v = (tid < NBLK_SCAN) ? g_bsum[tid] : 0;
    int x = v;
    #pragma unroll
    for (int d = 1; d < 32; d <<= 1) {
        int t = __shfl_up_sync(0xffffffffu, x, d);
        if (lane >= d) x += t;
    }
    if (lane == 31) ws[wid] = x;
    __syncthreads();
    int base = 0;
    for (int w = 0; w < wid; w++) base += ws[w];
    if (tid < NBLK_SCAN) g_boff[tid] = base + x - v;
}

__global__ void k_scan2() {
    __shared__ int ws[32];
    int tid = threadIdx.x, lane = tid & 31, wid = tid >> 5;
    int i = blockIdx.x * SCAN_BS + tid;
    int v = (i < NN) ? ((g_cnt[i] + 7) & ~7) : 0;
    int x = v;
    #pragma unroll
    for (int d = 1; d < 32; d <<= 1) {
        int t = __shfl_up_sync(0xffffffffu, x, d);
        if (lane >= d) x += t;
    }
    if (lane == 31) ws[wid] = x;
    __syncthreads();
    if (wid == 0) {
        int y = ws[lane];
        #pragma unroll
        for (int d = 1; d < 32; d <<= 1) {
            int t = __shfl_up_sync(0xffffffffu, y, d);
            if (lane >= d) y += t;
        }
        ws[lane] = y;
    }
    __syncthreads();
    int excl = g_boff[blockIdx.x] + (wid ? ws[wid - 1] : 0) + x - v;
    if (i < NN) {
        g_off[i] = excl;
        g_cur[i] = excl;
        if (i == NN - 1) g_off[NN] = excl + v;
    }
}

__global__ void k_scatter(const int* __restrict__ ei, const float* __restrict__ ew) {
    int e = blockIdx.x * blockDim.x + threadIdx.x;
    if (e < EE) {
        int r = ei[e], c = ei[EE + e];
        float nrm = g_dis[r] * ew[e] * g_dis[c];
        int p = atomicAdd(&g_cur[c], 1);
        g_csc[p] = make_int2(r, __float_as_int(nrm));
    }
}

// ---------------- layer 1: init + thread-per-node 2-wide hops ---------------
__global__ void k_init1(const float* __restrict__ c, const int* __restrict__ ip) {
    int n = blockIdx.x * blockDim.x + threadIdx.x;
    if (n >= NN) return;
    int iv = ip[0];
    ((float2*)g_h1)[n] = make_float2((n == iv) ? 1.f : 0.f, c[n]);
}

__global__ void __launch_bounds__(256) k_hop1(int k) {
    int n = blockIdx.x * blockDim.x + threadIdx.x;
    if (n >= NN) return;
    const float2* hc = (const float2*)g_h1 + (size_t)(k - 1) * NN;
    float2* hn = (float2*)g_h1 + (size_t)k * NN;
    int s = g_off[n], e = g_off[n + 1];     // multiples of 8
    const int4* c4 = (const int4*)g_csc;
    float ax = 0.f, ay = 0.f;
    for (int t = s; t < e; t += 8) {
        int h = t >> 1;
        int4 A = c4[h], B = c4[h + 1], C = c4[h + 2], D = c4[h + 3];
        float2 v0 = hc[A.x], v1 = hc[A.z], v2 = hc[B.x], v3 = hc[B.z];
        float2 v4 = hc[C.x], v5 = hc[C.z], v6 = hc[D.x], v7 = hc[D.z];
        float w0 = __int_as_float(A.y), w1 = __int_as_float(A.w);
        float w2 = __int_as_float(B.y), w3 = __int_as_float(B.w);
        float w4 = __int_as_float(C.y), w5 = __int_as_float(C.w);
        float w6 = __int_as_float(D.y), w7 = __int_as_float(D.w);
        ax = fmaf(w0, v0.x, ax); ay = fmaf(w0, v0.y, ay);
        ax = fmaf(w1, v1.x, ax); ay = fmaf(w1, v1.y, ay);
        ax = fmaf(w2, v2.x, ax); ay = fmaf(w2, v2.y, ay);
        ax = fmaf(w3, v3.x, ax); ay = fmaf(w3, v3.y, ay);
        ax = fmaf(w4, v4.x, ax); ay = fmaf(w4, v4.y, ay);
        ax = fmaf(w5, v5.x, ax); ay = fmaf(w5, v5.y, ay);
        ax = fmaf(w6, v6.x, ax); ay = fmaf(w6, v6.y, ay);
        ax = fmaf(w7, v7.x, ax); ay = fmaf(w7, v7.y, ay);
    }
    hn[n] = make_float2(ax, ay);
}

// ---- combine layer 1 (f32x2): acc1 = b1 + sum_k h1_k W1_k; relu -> h2[0] ---
__global__ void k_comb1(const float* __restrict__ W1, const float* __restrict__ b1) {
    __shared__ __align__(16) float sW[(KHOP + 1) * 30];
    __shared__ float sb[16];
    for (int i = threadIdx.x; i < (KHOP + 1) * 30; i += 256) sW[i] = W1[i];
    if (threadIdx.x < 16) sb[threadIdx.x] = (threadIdx.x < 15) ? b1[threadIdx.x] : 0.f;
    __syncthreads();
    int n = blockIdx.x * blockDim.x + threadIdx.x;
    if (n >= NN) return;
    unsigned long long ap[7];
    float a14 = sb[14];
    #pragma unroll
    for (int jp = 0; jp < 7; jp++) ap[jp] = pk2(sb[2 * jp], sb[2 * jp + 1]);
    for (int k = 0; k <= KHOP; k++) {
        float2 h = ((const float2*)g_h1)[(size_t)k * NN + n];
        const float* wk = &sW[k * 30];
        unsigned long long hx = pk2(h.x, h.x), hy = pk2(h.y, h.y);
        #pragma unroll
        for (int jp = 0; jp < 7; jp++) {
            unsigned long long wx = pk2(wk[2 * jp], wk[2 * jp + 1]);
            unsigned long long wy = pk2(wk[15 + 2 * jp], wk[15 + 2 * jp + 1]);
            fma2(ap[jp], hx, wx);
            fma2(ap[jp], hy, wy);
        }
        a14 = fmaf(h.x, wk[14], fmaf(h.y, wk[29], a14));
    }
    float v[16];
    #pragma unroll
    for (int jp = 0; jp < 7; jp++) {
        float a, b;
        upk2(a, b, ap[jp]);
        v[2 * jp] = fmaxf(a, 0.f);
        v[2 * jp + 1] = fmaxf(b, 0.f);
    }
    v[14] = fmaxf(a14, 0.f);
    v[15] = 0.f;
    float4* hp = (float4*)g_h2 + n * 4;   // slab 0
    hp[0] = *(float4*)(v + 0); hp[1] = *(float4*)(v + 4);
    hp[2] = *(float4*)(v + 8); hp[3] = *(float4*)(v + 12);
}

// ------- layer 2: 16-wide hops (4 lanes/node, 2 nodes/group) ----------------
__global__ void __launch_bounds__(256) k_hop2(int k) {
    int tid = threadIdx.x;
    int g = tid >> 2, l = tid & 3;
    const float4* hc = (const float4*)(g_h2 + (size_t)(k - 1) * NN * 16);
    float4* hn = (float4*)(g_h2 + (size_t)k * NN * 16);
    const int4* c4 = (const int4*)g_csc;
    #pragma unroll
    for (int half = 0; half < 2; half++) {
        int n = blockIdx.x * 128 + half * 64 + g;
        if (n >= NN) continue;
        int s = g_off[n], e = g_off[n + 1];
        float4 acc = make_float4(0.f, 0.f, 0.f, 0.f);
        for (int t = s; t < e; t += 4) {
            int h = t >> 1;
            int4 A = c4[h], B = c4[h + 1];
            float4 v0 = hc[A.x * 4 + l];
            float4 v1 = hc[A.z * 4 + l];
            float4 v2 = hc[B.x * 4 + l];
            float4 v3 = hc[B.z * 4 + l];
            float w0 = __int_as_float(A.y), w1 = __int_as_float(A.w);
            float w2 = __int_as_float(B.y), w3 = __int_as_float(B.w);
            acc.x = fmaf(w0, v0.x, acc.x); acc.y = fmaf(w0, v0.y, acc.y);
            acc.z = fmaf(w0, v0.z, acc.z); acc.w = fmaf(w0, v0.w, acc.w);
            acc.x = fmaf(w1, v1.x, acc.x); acc.y = fmaf(w1, v1.y, acc.y);
            acc.z = fmaf(w1, v1.z, acc.z); acc.w = fmaf(w1, v1.w, acc.w);
            acc.x = fmaf(w2, v2.x, acc.x); acc.y = fmaf(w2, v2.y, acc.y);
            acc.z = fmaf(w2, v2.z, acc.z); acc.w = fmaf(w2, v2.w, acc.w);
            acc.x = fmaf(w3, v3.x, acc.x); acc.y = fmaf(w3, v3.y, acc.y);
            acc.z = fmaf(w3, v3.z, acc.z); acc.w = fmaf(w3, v3.w, acc.w);
        }
        hn[n * 4 + l] = acc;
    }
}

// ---- fused combine: acc2 (phase A) then z3 slabs (phase B). All f32x2. -----
__global__ void k_comb2(const float* __restrict__ W2, const float* __restrict__ b2,
                        const float* __restrict__ W3, const float* __restrict__ b3) {
    __shared__ __align__(16) float sW[17 * 480];
    __shared__ float sb2[30];
    __shared__ float sb3[16];
    int tid = threadIdx.x;
    if (tid < 30) sb2[tid] = b2[tid];
    if (tid >= 32 && tid < 48) sb3[tid - 32] = (tid - 32 < 15) ? b3[tid - 32] : 0.f;
    int n = blockIdx.x * 256 + tid;
    unsigned long long accp[15];
    #pragma unroll
    for (int jp = 0; jp < 15; jp++) accp[jp] = 0ull;
    for (int kc = 0; kc < KHOP + 1; kc += 17) {
        __syncthreads();
        for (int i = tid; i < 17 * 450; i += 256) {
            int kk = kc + i / 450;
            if (kk <= KHOP) sW[i] = W2[kk * 450 + i % 450];
        }
        __syncthreads();
        if (n < NN) {
            int kmax = KHOP + 1 - kc; if (kmax > 17) kmax = 17;
            for (int dk = 0; dk < kmax; dk++) {
                int k = kc + dk;
                const float4* hp = (const float4*)(g_h2 + (size_t)k * NN * 16) + n * 4;
                float h[16];
                *(float4*)(h + 0) = hp[0]; *(float4*)(h + 4) = hp[1];
                *(float4*)(h + 8) = hp[2]; *(float4*)(h + 12) = hp[3];
                const float* wk = &sW[dk * 450];
                #pragma unroll
                for (int f = 0; f < 15; f++) {
                    unsigned long long hfp = pk2(h[f], h[f]);
                    const unsigned long long* wr =
                        (const unsigned long long*)(wk + f * 30);
                    #pragma unroll
                    for (int jp = 0; jp < 15; jp++) fma2(accp[jp], hfp, wr[jp]);
                }
            }
        }
    }
    float v[30];
    if (n < NN) {
        #pragma unroll
        for (int jp = 0; jp < 15; jp++) {
            float a, b;
            upk2(a, b, accp[jp]);
            v[2 * jp]     = fmaxf(a + sb2[2 * jp], 0.f);
            v[2 * jp + 1] = fmaxf(b + sb2[2 * jp + 1], 0.f);
        }
    }
    for (int kc = 0; kc < KHOP + 1; kc += 17) {
        __syncthreads();
        for (int i = tid; i < 17 * 480; i += 256) {
            int dk = i / 480, r = i % 480, f = r / 16, j = r % 16;
            int kk = kc + dk;
            sW[i] = (j < 15 && kk <= KHOP) ? W3[kk * 450 + f * 15 + j] : 0.f;
        }
        __syncthreads();
        if (n < NN) {
            int kmax = KHOP + 1 - kc; if (kmax > 17) kmax = 17;
            for (int dk = 0; dk < kmax; dk++) {
                int k = kc + dk;
                unsigned long long zp8[8];
                #pragma unroll
                for (int jp = 0; jp < 8; jp++)
                    zp8[jp] = (k == 0) ? pk2(sb3[2 * jp], sb3[2 * jp + 1]) : 0ull;
                const float* wk = &sW[dk * 480];
                #pragma unroll
                for (int f = 0; f < 30; f++) {
                    unsigned long long vfp = pk2(v[f], v[f]);
                    const unsigned long long* wr =
                        (const unsigned long long*)(wk + f * 16);
                    #pragma unroll
                    for (int jp = 0; jp < 8; jp++) fma2(zp8[jp], vfp, wr[jp]);
                }
                float z[16];
                #pragma unroll
                for (int jp = 0; jp < 8; jp++) upk2(z[2 * jp], z[2 * jp + 1], zp8[jp]);
                float4* zo = (float4*)(g_z3 + (size_t)k * NN * 16) + n * 4;
                zo[0] = *(float4*)(z + 0); zo[1] = *(float4*)(z + 4);
                zo[2] = *(float4*)(z + 8); zo[3] = *(float4*)(z + 12);
            }
        }
    }
}

// ------- layer 3 Horner hop: t_new = A t_old + z3_k (2 nodes/group) ---------
__global__ void __launch_bounds__(256) k_hop3(int first, int wsel, int kk) {
    int tid = threadIdx.x;
    int g = tid >> 2, l = tid & 3;
    const float4* t_old = first ? ((const float4*)(g_z3 + (size_t)KHOP * NN * 16))
                                : (wsel ? (const float4*)g_hb : (const float4*)g_ha);
    float4* t_new = wsel ? (float4*)g_ha : (float4*)g_hb;
    const float4* zp = (const float4*)(g_z3 + (size_t)kk * NN * 16);
    const int4* c4 = (const int4*)g_csc;
    #pragma unroll
    for (int half = 0; half < 2; half++) {
        int n = blockIdx.x * 128 + half * 64 + g;
        if (n >= NN) continue;
        int s = g_off[n], e = g_off[n + 1];
        float4 acc = make_float4(0.f, 0.f, 0.f, 0.f);
        for (int t = s; t < e; t += 4) {
            int h = t >> 1;
            int4 A = c4[h], B = c4[h + 1];
            float4 v0 = t_old[A.x * 4 + l];
            float4 v1 = t_old[A.z * 4 + l];
            float4 v2 = t_old[B.x * 4 + l];
            float4 v3 = t_old[B.z * 4 + l];
            float w0 = __int_as_float(A.y), w1 = __int_as_float(A.w);
            float w2 = __int_as_float(B.y), w3 = __int_as_float(B.w);
            acc.x = fmaf(w0, v0.x, acc.x); acc.y = fmaf(w0, v0.y, acc.y);
            acc.z = fmaf(w0, v0.z, acc.z); acc.w = fmaf(w0, v0.w, acc.w);
            acc.x = fmaf(w1, v1.x, acc.x); acc.y = fmaf(w1, v1.y, acc.y);
            acc.z = fmaf(w1, v1.z, acc.z); acc.w = fmaf(w1, v1.w, acc.w);
            acc.x = fmaf(w2, v2.x, acc.x); acc.y = fmaf(w2, v2.y, acc.y);
            acc.z = fmaf(w2, v2.z, acc.z); acc.w = fmaf(w2, v2.w, acc.w);
            acc.x = fmaf(w3, v3.x, acc.x); acc.y = fmaf(w3, v3.y, acc.y);
            acc.z = fmaf(w3, v3.z, acc.z); acc.w = fmaf(w3, v3.w, acc.w);
        }
        float4 z = zp[n * 4 + l];
        acc.x += z.x; acc.y += z.y; acc.z += z.z; acc.w += z.w;
        t_new[n * 4 + l] = acc;
    }
}

// ---- transition 3->4: x4 = relu(t3 in g_hb); z4[k][n] = x4 . W4_k ---------
__global__ void k_z4(const float* __restrict__ W4, const float* __restrict__ b4) {
    __shared__ float sW[(KHOP + 1) * 15];
    __shared__ float sb0;
    for (int idx = threadIdx.x; idx < (KHOP + 1) * 15; idx += 256) sW[idx] = W4[idx];
    if (threadIdx.x == 0) sb0 = b4[0];
    __syncthreads();
    int n = blockIdx.x * blockDim.x + threadIdx.x;
    if (n >= NN) return;
    float v[16];
    const float4* tp = (const float4*)(g_hb + n * 16);  // final t3 in g_hb (50 hops)
    *(float4*)(v + 0) = tp[0]; *(float4*)(v + 4) = tp[1];
    *(float4*)(v + 8) = tp[2]; *(float4*)(v + 12) = tp[3];
    #pragma unroll
    for (int f = 0; f < 15; f++) v[f] = fmaxf(v[f], 0.f);
    for (int k = 0; k <= KHOP; k++) {
        float z = (k == 0) ? sb0 : 0.f;
        #pragma unroll
        for (int f = 0; f < 15; f++) z = fmaf(v[f], sW[k * 15 + f], z);
        g_z4[(size_t)k * NN + n] = z;
    }
}

// ------------- layer 4 Horner hop (thread-per-node, int4 edge loads) --------
// mode: 0 -> told = g_z4[KHOP], 1 -> told = g_t4a, 2 -> told = g_t4b
__global__ void __launch_bounds__(256) k_hop4(int mode, int wout, int kidx,
                                              int fin, float* __restrict__ out) {
    int n = blockIdx.x * blockDim.x + threadIdx.x;
    if (n >= NN) return;
    const float* told = (mode == 0) ? (g_z4 + (size_t)KHOP * NN)
                                    : (mode == 1 ? g_t4a : g_t4b);
    float* tnew = wout ? g_t4b : g_t4a;
    int s = g_off[n], e = g_off[n + 1];
    const int4* c4 = (const int4*)g_csc;
    float sum = 0.f;
    for (int t = s; t < e; t += 8) {
        int h = t >> 1;
        int4 A = c4[h], B = c4[h + 1], C = c4[h + 2], D = c4[h + 3];
        float v0 = __ldg(told + A.x), v1 = __ldg(told + A.z);
        float v2 = __ldg(told + B.x), v3 = __ldg(told + B.z);
        float v4 = __ldg(told + C.x), v5 = __ldg(told + C.z);
        float v6 = __ldg(told + D.x), v7 = __ldg(told + D.z);
        sum = fmaf(__int_as_float(A.y), v0, sum);
        sum = fmaf(__int_as_float(A.w), v1, sum);
        sum = fmaf(__int_as_float(B.y), v2, sum);
        sum = fmaf(__int_as_float(B.w), v3, sum);
        sum = fmaf(__int_as_float(C.y), v4, sum);
        sum = fmaf(__int_as_float(C.w), v5, sum);
        sum = fmaf(__int_as_float(D.y), v6, sum);
        sum = fmaf(__int_as_float(D.w), v7, sum);
    }
    float r = g_z4[(size_t)kidx * NN + n] + sum;
    if (fin) out[n] = fmaxf(r, 0.f);
    else tnew[n] = r;
}

// ---------------- host launch ----------------
static inline int div_up(int a, int b) { return (a + b - 1) / b; }

extern "C" void kernel_launch(void* const* d_in, const int* in_sizes, int n_in,
                              void* d_out, int out_size) {
    const int*   ei = (const int*)d_in[0];
    const float* ew = (const float*)d_in[1];
    const float* c  = (const float*)d_in[2];
    const int*   ip = (const int*)d_in[3];
    const float* W1 = (const float*)d_in[4];
    const float* b1 = (const float*)d_in[5];
    const float* W2 = (const float*)d_in[6];
    const float* b2 = (const float*)d_in[7];
    const float* W3 = (const float*)d_in[8];
    const float* b3 = (const float*)d_in[9];
    const float* W4 = (const float*)d_in[10];
    const float* b4 = (const float*)d_in[11];
    float* out = (float*)d_out;

    int nb = div_up(NN, 256);
    int eb = div_up(EE, 256);
    int hb2 = div_up(NN, 128);   // wide hop kernels: 2 nodes per 4-lane group

    // graph preprocessing (padded CSC)
    k_init0<<<div_up(CSCSZ / 2, 256), 256>>>();
    k_degcnt<<<eb, 256>>>(ei, ew);
    k_bsum<<<NBLK_SCAN, SCAN_BS>>>();
    k_bscan<<<1, 128>>>();
    k_scan2<<<NBLK_SCAN, SCAN_BS>>>();
    k_scatter<<<eb, 256>>>(ei, ew);

    // layer 1: hops into slabs, then combine
    k_init1<<<nb, 256>>>(c, ip);
    for (int k = 1; k <= KHOP; k++) k_hop1<<<nb, 256>>>(k);
    k_comb1<<<nb, 256>>>(W1, b1);

    // layer 2: hops into slabs, then fused combine (acc2 + z3 precompute)
    for (int k = 1; k <= KHOP; k++) k_hop2<<<hb2, 256>>>(k);
    k_comb2<<<nb, 256>>>(W2, b2, W3, b3);

    // layer 3: Horner hops
    for (int idx = 0; idx < KHOP; idx++) {
        int k = KHOP - 1 - idx;
        k_hop3<<<hb2, 256>>>((idx == 0) ? 1 : 0, ((idx & 1) == 0) ? 1 : 0, k);
    }
    // idx even writes g_ha, idx odd writes g_hb; idx=49 (odd) -> final in g_hb

    // layer 4: Horner hops with precomputed z; final writes out
    k_z4<<<nb, 256>>>(W4, b4);
    int mode = 0, w = 0;
    for (int k = KHOP - 1; k >= 0; k--) {
        k_hop4<<<nb, 256>>>(mode, w, k, (k == 0) ? 1 : 0, out);
        mode = w ? 2 : 1;
        w ^= 1;
    }
}

// round 16
// speedup vs baseline: 1.0649x; 1.0649x over previous
#include <cuda_runtime.h>

#define NN 100000
#define EE 1600000
#define KHOP 50
#define SCAN_BS 1024
#define NBLK_SCAN ((NN + SCAN_BS - 1) / SCAN_BS)
#define CSCSZ (EE + 3 * NN + 64)   // deg padded to multiple of 4

// ---------------- device scratch (static, no allocation) ----------------
__device__ float g_deg[NN];
__device__ float g_dis[NN];
__device__ int   g_cnt[NN];
__device__ int   g_off[NN + 1];
__device__ int   g_cur[NN];
__device__ int   g_bsum[NBLK_SCAN];
__device__ int   g_boff[NBLK_SCAN];
__device__ __align__(16) int2 g_csc[CSCSZ];          // {src, bitcast(norm)}; zero-padded
__device__ float g_h1[(KHOP + 1) * NN * 2];          // layer-1 hop history (2-wide)
__device__ float g_h2[(size_t)(KHOP + 1) * NN * 16]; // layer-2 hop history (16-wide)
__device__ float g_z3[(size_t)(KHOP + 1) * NN * 16]; // layer-3 z_k = x3 W3_k (16-wide)
__device__ float g_ha[NN * 16];                      // layer-3 Horner ping
__device__ float g_hb[NN * 16];                      // layer-3 Horner pong
__device__ float g_z4[(KHOP + 1) * NN];
__device__ float g_t4a[NN];
__device__ float g_t4b[NN];

// ---------------- f32x2 packed helpers (bitwise-identical fp32 math) --------
__device__ __forceinline__ unsigned long long pk2(float lo, float hi) {
    unsigned long long r;
    asm("mov.b64 %0, {%1, %2};" : "=l"(r) : "f"(lo), "f"(hi));
    return r;
}
__device__ __forceinline__ void upk2(float& lo, float& hi, unsigned long long v) {
    asm("mov.b64 {%0, %1}, %2;" : "=f"(lo), "=f"(hi) : "l"(v));
}
__device__ __forceinline__ void fma2(unsigned long long& d, unsigned long long a,
                                     unsigned long long b) {
    asm("fma.rn.f32x2 %0, %1, %2, %0;" : "+l"(d) : "l"(a), "l"(b));
}

// ---------------- setup kernels ----------------
__global__ void k_init0() {
    int i = blockIdx.x * blockDim.x + threadIdx.x;
    if (i < NN) { g_deg[i] = 0.f; g_cnt[i] = 0; }
    if (i < CSCSZ / 2) ((int4*)g_csc)[i] = make_int4(0, 0, 0, 0);
}

__global__ void k_degcnt(const int* __restrict__ ei, const float* __restrict__ ew) {
    int e = blockIdx.x * blockDim.x + threadIdx.x;
    if (e < EE) {
        int c = ei[EE + e];
        atomicAdd(&g_deg[c], ew[e]);
        atomicAdd(&g_cnt[c], 1);
    }
}

// per-block sums of PADDED counts (multiple of 4) + fused g_dis computation
__global__ void k_bsum() {
    __shared__ int ws[32];
    int tid = threadIdx.x, lane = tid & 31, wid = tid >> 5;
    int i = blockIdx.x * SCAN_BS + tid;
    int v = 0;
    if (i < NN) {
        v = (g_cnt[i] + 3) & ~3;
        float d = g_deg[i];
        g_dis[i] = (d > 0.f) ? (1.0f / sqrtf(d)) : 0.f;
    }
    #pragma unroll
    for (int d = 16; d >= 1; d >>= 1) v += __shfl_down_sync(0xffffffffu, v, d);
    if (lane == 0) ws[wid] = v;
    __syncthreads();
    if (wid == 0) {
        int y = ws[lane];
        #pragma unroll
        for (int d = 16; d >= 1; d >>= 1) y += __shfl_down_sync(0xffffffffu, y, d);
        if (lane == 0) g_bsum[blockIdx.x] = y;
    }
}

__global__ void k_bscan() {
    __shared__ int ws[4];
    int tid = threadIdx.x, lane = tid & 31, wid = tid >> 5;
    int v = (tid < NBLK_SCAN) ? g_bsum[tid] : 0;
    int x = v;
    #pragma unroll
    for (int d = 1; d < 32; d <<= 1) {
        int t = __shfl_up_sync(0xffffffffu, x, d);
        if (lane >= d) x += t;
    }
    if (lane == 31) ws[wid] = x;
    __syncthreads();
    int base = 0;
    for (int w = 0; w < wid; w++) base += ws[w];
    if (tid < NBLK_SCAN) g_boff[tid] = base + x - v;
}

__global__ void k_scan2() {
    __shared__ int ws[32];
    int tid = threadIdx.x, lane = tid & 31, wid = tid >> 5;
    int i = blockIdx.x * SCAN_BS + tid;
    int v = (i < NN) ? ((g_cnt[i] + 3) & ~3) : 0;
    int x = v;
    #pragma unroll
    for (int d = 1; d < 32; d <<= 1) {
        int t = __shfl_up_sync(0xffffffffu, x, d);
        if (lane >= d) x += t;
    }
    if (lane == 31) ws[wid] = x;
    __syncthreads();
    if (wid == 0) {
        int y = ws[lane];
        #pragma unroll
        for (int d = 1; d < 32; d <<= 1) {
            int t = __shfl_up_sync(0xffffffffu, y, d);
            if (lane >= d) y += t;
        }
        ws[lane] = y;
    }
    __syncthreads();
    int excl = g_boff[blockIdx.x] + (wid ? ws[wid - 1] : 0) + x - v;
    if (i < NN) {
        g_off[i] = excl;
        g_cur[i] = excl;
        if (i == NN - 1) g_off[NN] = excl + v;
    }
}

__global__ void k_scatter(const int* __restrict__ ei, const float* __restrict__ ew) {
    int e = blockIdx.x * blockDim.x + threadIdx.x;
    if (e < EE) {
        int r = ei[e], c = ei[EE + e];
        float nrm = g_dis[r] * ew[e] * g_dis[c];
        int p = atomicAdd(&g_cur[c], 1);
        g_csc[p] = make_int2(r, __float_as_int(nrm));
    }
}

// ---------------- layer 1: init + thread-per-node 2-wide hops ---------------
__global__ void k_init1(const float* __restrict__ c, const int* __restrict__ ip) {
    int n = blockIdx.x * blockDim.x + threadIdx.x;
    if (n >= NN) return;
    int iv = ip[0];
    ((float2*)g_h1)[n] = make_float2((n == iv) ? 1.f : 0.f, c[n]);
}

__global__ void __launch_bounds__(256) k_hop1(int k) {
    int n = blockIdx.x * blockDim.x + threadIdx.x;
    if (n >= NN) return;
    const float2* hc = (const float2*)g_h1 + (size_t)(k - 1) * NN;
    float2* hn = (float2*)g_h1 + (size_t)k * NN;
    int s = g_off[n], e = g_off[n + 1];     // multiples of 4
    const int4* c4 = (const int4*)g_csc;
    float ax = 0.f, ay = 0.f;
    for (int t = s; t < e; t += 4) {
        int h = t >> 1;
        int4 A = c4[h], B = c4[h + 1];
        float2 v0 = hc[A.x], v1 = hc[A.z], v2 = hc[B.x], v3 = hc[B.z];
        float w0 = __int_as_float(A.y), w1 = __int_as_float(A.w);
        float w2 = __int_as_float(B.y), w3 = __int_as_float(B.w);
        ax = fmaf(w0, v0.x, ax); ay = fmaf(w0, v0.y, ay);
        ax = fmaf(w1, v1.x, ax); ay = fmaf(w1, v1.y, ay);
        ax = fmaf(w2, v2.x, ax); ay = fmaf(w2, v2.y, ay);
        ax = fmaf(w3, v3.x, ax); ay = fmaf(w3, v3.y, ay);
    }
    hn[n] = make_float2(ax, ay);
}

// ---- combine layer 1 (f32x2): acc1 = b1 + sum_k h1_k W1_k; relu -> h2[0] ---
__global__ void k_comb1(const float* __restrict__ W1, const float* __restrict__ b1) {
    __shared__ __align__(16) float sW[(KHOP + 1) * 30];
    __shared__ float sb[16];
    for (int i = threadIdx.x; i < (KHOP + 1) * 30; i += 256) sW[i] = W1[i];
    if (threadIdx.x < 16) sb[threadIdx.x] = (threadIdx.x < 15) ? b1[threadIdx.x] : 0.f;
    __syncthreads();
    int n = blockIdx.x * blockDim.x + threadIdx.x;
    if (n >= NN) return;
    unsigned long long ap[7];
    float a14 = sb[14];
    #pragma unroll
    for (int jp = 0; jp < 7; jp++) ap[jp] = pk2(sb[2 * jp], sb[2 * jp + 1]);
    for (int k = 0; k <= KHOP; k++) {
        float2 h = ((const float2*)g_h1)[(size_t)k * NN + n];
        const float* wk = &sW[k * 30];
        unsigned long long hx = pk2(h.x, h.x), hy = pk2(h.y, h.y);
        #pragma unroll
        for (int jp = 0; jp < 7; jp++) {
            unsigned long long wx = pk2(wk[2 * jp], wk[2 * jp + 1]);
            unsigned long long wy = pk2(wk[15 + 2 * jp], wk[15 + 2 * jp + 1]);
            fma2(ap[jp], hx, wx);
            fma2(ap[jp], hy, wy);
        }
        a14 = fmaf(h.x, wk[14], fmaf(h.y, wk[29], a14));
    }
    float v[16];
    #pragma unroll
    for (int jp = 0; jp < 7; jp++) {
        float a, b;
        upk2(a, b, ap[jp]);
        v[2 * jp] = fmaxf(a, 0.f);
        v[2 * jp + 1] = fmaxf(b, 0.f);
    }
    v[14] = fmaxf(a14, 0.f);
    v[15] = 0.f;
    float4* hp = (float4*)g_h2 + n * 4;   // slab 0
    hp[0] = *(float4*)(v + 0); hp[1] = *(float4*)(v + 4);
    hp[2] = *(float4*)(v + 8); hp[3] = *(float4*)(v + 12);
}

// ------- layer 2: 16-wide hops (4 lanes/node, 4-edge unroll) ----------------
__global__ void __launch_bounds__(256) k_hop2(int k) {
    int tid = threadIdx.x;
    int g = tid >> 2, l = tid & 3;
    int n = blockIdx.x * 64 + g;
    if (n >= NN) return;
    const float4* hc = (const float4*)(g_h2 + (size_t)(k - 1) * NN * 16);
    float4* hn = (float4*)(g_h2 + (size_t)k * NN * 16);
    int s = g_off[n], e = g_off[n + 1];
    const int4* c4 = (const int4*)g_csc;
    float4 acc = make_float4(0.f, 0.f, 0.f, 0.f);
    for (int t = s; t < e; t += 4) {
        int h = t >> 1;
        int4 A = c4[h], B = c4[h + 1];
        float4 v0 = hc[A.x * 4 + l];
        float4 v1 = hc[A.z * 4 + l];
        float4 v2 = hc[B.x * 4 + l];
        float4 v3 = hc[B.z * 4 + l];
        float w0 = __int_as_float(A.y), w1 = __int_as_float(A.w);
        float w2 = __int_as_float(B.y), w3 = __int_as_float(B.w);
        acc.x = fmaf(w0, v0.x, acc.x); acc.y = fmaf(w0, v0.y, acc.y);
        acc.z = fmaf(w0, v0.z, acc.z); acc.w = fmaf(w0, v0.w, acc.w);
        acc.x = fmaf(w1, v1.x, acc.x); acc.y = fmaf(w1, v1.y, acc.y);
        acc.z = fmaf(w1, v1.z, acc.z); acc.w = fmaf(w1, v1.w, acc.w);
        acc.x = fmaf(w2, v2.x, acc.x); acc.y = fmaf(w2, v2.y, acc.y);
        acc.z = fmaf(w2, v2.z, acc.z); acc.w = fmaf(w2, v2.w, acc.w);
        acc.x = fmaf(w3, v3.x, acc.x); acc.y = fmaf(w3, v3.y, acc.y);
        acc.z = fmaf(w3, v3.z, acc.z); acc.w = fmaf(w3, v3.w, acc.w);
    }
    hn[n * 4 + l] = acc;
}

// ---- fused combine: acc2 (phase A) then z3 slabs (phase B). All f32x2. -----
__global__ void k_comb2(const float* __restrict__ W2, const float* __restrict__ b2,
                        const float* __restrict__ W3, const float* __restrict__ b3) {
    __shared__ __align__(16) float sW[17 * 480];
    __shared__ float sb2[30];
    __shared__ float sb3[16];
    int tid = threadIdx.x;
    if (tid < 30) sb2[tid] = b2[tid];
    if (tid >= 32 && tid < 48) sb3[tid - 32] = (tid - 32 < 15) ? b3[tid - 32] : 0.f;
    int n = blockIdx.x * 256 + tid;
    unsigned long long accp[15];
    #pragma unroll
    for (int jp = 0; jp < 15; jp++) accp[jp] = 0ull;
    for (int kc = 0; kc < KHOP + 1; kc += 17) {
        __syncthreads();
        for (int i = tid; i < 17 * 450; i += 256) {
            int kk = kc + i / 450;
            if (kk <= KHOP) sW[i] = W2[kk * 450 + i % 450];
        }
        __syncthreads();
        if (n < NN) {
            int kmax = KHOP + 1 - kc; if (kmax > 17) kmax = 17;
            for (int dk = 0; dk < kmax; dk++) {
                int k = kc + dk;
                const float4* hp = (const float4*)(g_h2 + (size_t)k * NN * 16) + n * 4;
                float h[16];
                *(float4*)(h + 0) = hp[0]; *(float4*)(h + 4) = hp[1];
                *(float4*)(h + 8) = hp[2]; *(float4*)(h + 12) = hp[3];
                const float* wk = &sW[dk * 450];
                #pragma unroll
                for (int f = 0; f < 15; f++) {
                    unsigned long long hfp = pk2(h[f], h[f]);
                    const unsigned long long* wr =
                        (const unsigned long long*)(wk + f * 30);
                    #pragma unroll
                    for (int jp = 0; jp < 15; jp++) fma2(accp[jp], hfp, wr[jp]);
                }
            }
        }
    }
    float v[30];
    if (n < NN) {
        #pragma unroll
        for (int jp = 0; jp < 15; jp++) {
            float a, b;
            upk2(a, b, accp[jp]);
            v[2 * jp]     = fmaxf(a + sb2[2 * jp], 0.f);
            v[2 * jp + 1] = fmaxf(b + sb2[2 * jp + 1], 0.f);
        }
    }
    for (int kc = 0; kc < KHOP + 1; kc += 17) {
        __syncthreads();
        for (int i = tid; i < 17 * 480; i += 256) {
            int dk = i / 480, r = i % 480, f = r / 16, j = r % 16;
            int kk = kc + dk;
            sW[i] = (j < 15 && kk <= KHOP) ? W3[kk * 450 + f * 15 + j] : 0.f;
        }
        __syncthreads();
        if (n < NN) {
            int kmax = KHOP + 1 - kc; if (kmax > 17) kmax = 17;
            for (int dk = 0; dk < kmax; dk++) {
                int k = kc + dk;
                unsigned long long zp8[8];
                #pragma unroll
                for (int jp = 0; jp < 8; jp++)
                    zp8[jp] = (k == 0) ? pk2(sb3[2 * jp], sb3[2 * jp + 1]) : 0ull;
                const float* wk = &sW[dk * 480];
                #pragma unroll
                for (int f = 0; f < 30; f++) {
                    unsigned long long vfp = pk2(v[f], v[f]);
                    const unsigned long long* wr =
                        (const unsigned long long*)(wk + f * 16);
                    #pragma unroll
                    for (int jp = 0; jp < 8; jp++) fma2(zp8[jp], vfp, wr[jp]);
                }
                float z[16];
                #pragma unroll
                for (int jp = 0; jp < 8; jp++) upk2(z[2 * jp], z[2 * jp + 1], zp8[jp]);
                float4* zo = (float4*)(g_z3 + (size_t)k * NN * 16) + n * 4;
                zo[0] = *(float4*)(z + 0); zo[1] = *(float4*)(z + 4);
                zo[2] = *(float4*)(z + 8); zo[3] = *(float4*)(z + 12);
            }
        }
    }
}

// ------- layer 3 Horner hop: t_new = A t_old + z3_k (4-edge unroll) ---------
__global__ void __launch_bounds__(256) k_hop3(int first, int wsel, int kk) {
    int tid = threadIdx.x;
    int g = tid >> 2, l = tid & 3;
    int n = blockIdx.x * 64 + g;
    if (n >= NN) return;
    const float4* t_old = first ? ((const float4*)(g_z3 + (size_t)KHOP * NN * 16))
                                : (wsel ? (const float4*)g_hb : (const float4*)g_ha);
    float4* t_new = wsel ? (float4*)g_ha : (float4*)g_hb;
    int s = g_off[n], e = g_off[n + 1];
    const int4* c4 = (const int4*)g_csc;
    float4 acc = make_float4(0.f, 0.f, 0.f, 0.f);
    for (int t = s; t < e; t += 4) {
        int h = t >> 1;
        int4 A = c4[h], B = c4[h + 1];
        float4 v0 = t_old[A.x * 4 + l];
        float4 v1 = t_old[A.z * 4 + l];
        float4 v2 = t_old[B.x * 4 + l];
        float4 v3 = t_old[B.z * 4 + l];
        float w0 = __int_as_float(A.y), w1 = __int_as_float(A.w);
        float w2 = __int_as_float(B.y), w3 = __int_as_float(B.w);
        acc.x = fmaf(w0, v0.x, acc.x); acc.y = fmaf(w0, v0.y, acc.y);
        acc.z = fmaf(w0, v0.z, acc.z); acc.w = fmaf(w0, v0.w, acc.w);
        acc.x = fmaf(w1, v1.x, acc.x); acc.y = fmaf(w1, v1.y, acc.y);
        acc.z = fmaf(w1, v1.z, acc.z); acc.w = fmaf(w1, v1.w, acc.w);
        acc.x = fmaf(w2, v2.x, acc.x); acc.y = fmaf(w2, v2.y, acc.y);
        acc.z = fmaf(w2, v2.z, acc.z); acc.w = fmaf(w2, v2.w, acc.w);
        acc.x = fmaf(w3, v3.x, acc.x); acc.y = fmaf(w3, v3.y, acc.y);
        acc.z = fmaf(w3, v3.z, acc.z); acc.w = fmaf(w3, v3.w, acc.w);
    }
    float4 z = ((const float4*)(g_z3 + (size_t)kk * NN * 16))[n * 4 + l];
    acc.x += z.x; acc.y += z.y; acc.z += z.z; acc.w += z.w;
    t_new[n * 4 + l] = acc;
}

// ---- transition 3->4: x4 = relu(t3 in g_hb); z4[k][n] = x4 . W4_k ---------
__global__ void k_z4(const float* __restrict__ W4, const float* __restrict__ b4) {
    __shared__ float sW[(KHOP + 1) * 15];
    __shared__ float sb0;
    for (int idx = threadIdx.x; idx < (KHOP + 1) * 15; idx += 256) sW[idx] = W4[idx];
    if (threadIdx.x == 0) sb0 = b4[0];
    __syncthreads();
    int n = blockIdx.x * blockDim.x + threadIdx.x;
    if (n >= NN) return;
    float v[16];
    const float4* tp = (const float4*)(g_hb + n * 16);  // final t3 in g_hb (50 hops)
    *(float4*)(v + 0) = tp[0]; *(float4*)(v + 4) = tp[1];
    *(float4*)(v + 8) = tp[2]; *(float4*)(v + 12) = tp[3];
    #pragma unroll
    for (int f = 0; f < 15; f++) v[f] = fmaxf(v[f], 0.f);
    for (int k = 0; k <= KHOP; k++) {
        float z = (k == 0) ? sb0 : 0.f;
        #pragma unroll
        for (int f = 0; f < 15; f++) z = fmaf(v[f], sW[k * 15 + f], z);
        g_z4[(size_t)k * NN + n] = z;
    }
}

// ------------- layer 4 Horner hop (thread-per-node, 4-edge unroll) ----------
// mode: 0 -> told = g_z4[KHOP], 1 -> told = g_t4a, 2 -> told = g_t4b
__global__ void __launch_bounds__(256) k_hop4(int mode, int wout, int kidx,
                                              int fin, float* __restrict__ out) {
    int n = blockIdx.x * blockDim.x + threadIdx.x;
    if (n >= NN) return;
    const float* told = (mode == 0) ? (g_z4 + (size_t)KHOP * NN)
                                    : (mode == 1 ? g_t4a : g_t4b);
    float* tnew = wout ? g_t4b : g_t4a;
    int s = g_off[n], e = g_off[n + 1];
    const int4* c4 = (const int4*)g_csc;
    float sum = 0.f;
    for (int t = s; t < e; t += 4) {
        int h = t >> 1;
        int4 A = c4[h], B = c4[h + 1];
        float v0 = __ldg(told + A.x), v1 = __ldg(told + A.z);
        float v2 = __ldg(told + B.x), v3 = __ldg(told + B.z);
        sum = fmaf(__int_as_float(A.y), v0, sum);
        sum = fmaf(__int_as_float(A.w), v1, sum);
        sum = fmaf(__int_as_float(B.y), v2, sum);
        sum = fmaf(__int_as_float(B.w), v3, sum);
    }
    float r = g_z4[(size_t)kidx * NN + n] + sum;
    if (fin) out[n] = fmaxf(r, 0.f);
    else tnew[n] = r;
}

// ---------------- host launch ----------------
static inline int div_up(int a, int b) { return (a + b - 1) / b; }

extern "C" void kernel_launch(void* const* d_in, const int* in_sizes, int n_in,
                              void* d_out, int out_size) {
    const int*   ei = (const int*)d_in[0];
    const float* ew = (const float*)d_in[1];
    const float* c  = (const float*)d_in[2];
    const int*   ip = (const int*)d_in[3];
    const float* W1 = (const float*)d_in[4];
    const float* b1 = (const float*)d_in[5];
    const float* W2 = (const float*)d_in[6];
    const float* b2 = (const float*)d_in[7];
    const float* W3 = (const float*)d_in[8];
    const float* b3 = (const float*)d_in[9];
    const float* W4 = (const float*)d_in[10];
    const float* b4 = (const float*)d_in[11];
    float* out = (float*)d_out;

    int nb = div_up(NN, 256);
    int eb = div_up(EE, 256);
    int hb = div_up(NN, 64);   // 4 lanes/node hop kernels (R13 grid)

    // graph preprocessing (padded CSC, multiple of 4)
    k_init0<<<div_up(CSCSZ / 2, 256), 256>>>();
    k_degcnt<<<eb, 256>>>(ei, ew);
    k_bsum<<<NBLK_SCAN, SCAN_BS>>>();
    k_bscan<<<1, 128>>>();
    k_scan2<<<NBLK_SCAN, SCAN_BS>>>();
    k_scatter<<<eb, 256>>>(ei, ew);

    // layer 1: hops into slabs, then combine
    k_init1<<<nb, 256>>>(c, ip);
    for (int k = 1; k <= KHOP; k++) k_hop1<<<nb, 256>>>(k);
    k_comb1<<<nb, 256>>>(W1, b1);

    // layer 2: hops into slabs, then fused combine (acc2 + z3 precompute)
    for (int k = 1; k <= KHOP; k++) k_hop2<<<hb, 256>>>(k);
    k_comb2<<<nb, 256>>>(W2, b2, W3, b3);

    // layer 3: Horner hops
    for (int idx = 0; idx < KHOP; idx++) {
        int k = KHOP - 1 - idx;
        k_hop3<<<hb, 256>>>((idx == 0) ? 1 : 0, ((idx & 1) == 0) ? 1 : 0, k);
    }
    // idx even writes g_ha, idx odd writes g_hb; idx=49 (odd) -> final in g_hb

    // layer 4: Horner hops with precomputed z; final writes out
    k_z4<<<nb, 256>>>(W4, b4);
    int mode = 0, w = 0;
    for (int k = KHOP - 1; k >= 0; k--) {
        k_hop4<<<nb, 256>>>(mode, w, k, (k == 0) ? 1 : 0, out);
        mode = w ? 2 : 1;
        w ^= 1;
    }
}